// round 4
// baseline (speedup 1.0000x reference)
#include <cuda_runtime.h>

#define HIDN 50
#define KB 10
#define TDN 8
#define BBOUND 3.0f
#define TPB 128
#define PAD 52
#define MAXBLK 8192

// smem offsets (floats), all 16B-aligned
#define OFF_W0T 0                 // 50*8   = 400
#define OFF_B0  400               // pad to 52
#define OFF_W1T 452               // 50*52  = 2600
#define OFF_B1  3052              // pad to 52
#define OFF_WWT 3104              // 80*52  = 4160 (prescaled by 6)
#define OFF_BW  7264              // 80 (prescaled by 6)
#define OFF_WHT 7344              // 80*52  = 4160 (prescaled by 6)
#define OFF_BH  11504             // 80 (prescaled by 6)
#define OFF_WDT 11584             // 72*52  = 3744
#define OFF_BD  15328             // 72
#define SMEM_FLOATS 15400
#define SMEM_BYTES (SMEM_FLOATS * 4)

__device__ float g_partial[MAXBLK];
__device__ unsigned int g_count = 0;

__device__ __forceinline__ float ftanh(float v) {
    float e = __expf(2.0f * v);
    return 1.0f - __fdividef(2.0f, e + 1.0f);
}

// cheap softplus: args here are bounded (|v| <~ 5), so log(1+e^v) direct is safe
__device__ __forceinline__ float fsoftplus(float v) {
    return __logf(1.0f + __expf(v));
}

// single-row dot of 52 (last 2 pads are zero)
__device__ __forceinline__ float dot52(const float* __restrict__ h,
                                       const float* __restrict__ w) {
    float a0 = 0.f, a1 = 0.f, a2 = 0.f, a3 = 0.f;
#pragma unroll
    for (int q = 0; q < 13; q++) {
        float4 w4 = reinterpret_cast<const float4*>(w)[q];
        a0 = fmaf(h[4 * q + 0], w4.x, a0);
        a1 = fmaf(h[4 * q + 1], w4.y, a1);
        a2 = fmaf(h[4 * q + 2], w4.z, a2);
        a3 = fmaf(h[4 * q + 3], w4.w, a3);
    }
    return (a0 + a1) + (a2 + a3);
}

// two-row dot sharing one weight load stream
__device__ __forceinline__ void dot52x2(const float* __restrict__ g0,
                                        const float* __restrict__ g1,
                                        const float* __restrict__ w,
                                        float& r0, float& r1) {
    float a0 = 0.f, a1 = 0.f, a2 = 0.f, a3 = 0.f;
    float c0 = 0.f, c1 = 0.f, c2 = 0.f, c3 = 0.f;
#pragma unroll
    for (int q = 0; q < 13; q++) {
        float4 w4 = reinterpret_cast<const float4*>(w)[q];
        a0 = fmaf(g0[4 * q + 0], w4.x, a0);
        c0 = fmaf(g1[4 * q + 0], w4.x, c0);
        a1 = fmaf(g0[4 * q + 1], w4.y, a1);
        c1 = fmaf(g1[4 * q + 1], w4.y, c1);
        a2 = fmaf(g0[4 * q + 2], w4.z, a2);
        c2 = fmaf(g1[4 * q + 2], w4.z, c2);
        a3 = fmaf(g0[4 * q + 3], w4.w, a3);
        c3 = fmaf(g1[4 * q + 3], w4.w, c3);
    }
    r0 = (a0 + a1) + (a2 + a3);
    r1 = (c0 + c1) + (c2 + c3);
}

// full MLP for one row: zd[8] -> g[52] (pads zeroed)
__device__ __forceinline__ void mlp_row(const float* __restrict__ sm,
                                        const float* __restrict__ zd,
                                        float* __restrict__ g) {
    float h[PAD];
#pragma unroll
    for (int j = 0; j < HIDN; j++) {
        const float4* wv = reinterpret_cast<const float4*>(&sm[OFF_W0T + j * 8]);
        float4 a = wv[0], b = wv[1];
        float acc = sm[OFF_B0 + j];
        acc = fmaf(zd[0], a.x, acc);
        acc = fmaf(zd[1], a.y, acc);
        acc = fmaf(zd[2], a.z, acc);
        acc = fmaf(zd[3], a.w, acc);
        acc = fmaf(zd[4], b.x, acc);
        acc = fmaf(zd[5], b.y, acc);
        acc = fmaf(zd[6], b.z, acc);
        acc = fmaf(zd[7], b.w, acc);
        h[j] = ftanh(acc);
    }
    h[50] = 0.f; h[51] = 0.f;
#pragma unroll
    for (int j = 0; j < HIDN; j++) {
        g[j] = ftanh(dot52(h, &sm[OFF_W1T + j * PAD]) + sm[OFF_B1 + j]);
    }
    g[50] = 0.f; g[51] = 0.f;
}

// spline for one dim of one row, given raw exp'd logits + dv(bins 1..9)
__device__ __forceinline__ float spline_eval(float uu, const float* __restrict__ ew,
                                             const float* __restrict__ eh,
                                             const float* __restrict__ dv,
                                             float sw, float sh, float& z) {
    bool inside = (uu > -BBOUND) && (uu < BBOUND);
    float uc = fminf(fmaxf(uu, -BBOUND), BBOUND);

    float tw = (uc + BBOUND) * sw * (1.0f / 6.0f);
    float cw = 0.f, cy = 0.f;
    float csel = 0.f, cysel = 0.f;
    float wsel = ew[0], hsel = eh[0];
    float dk = 1.0f, dk1 = dv[0];
#pragma unroll
    for (int kk = 1; kk < KB; kk++) {
        cw += ew[kk - 1];
        cy += eh[kk - 1];
        if (cw <= tw) {
            csel = cw; cysel = cy;
            wsel = ew[kk]; hsel = eh[kk];
            dk = dv[kk - 1];
            dk1 = (kk == KB - 1) ? 1.0f : dv[kk];
        }
    }

    float inv_sh = __fdividef(1.0f, sh);
    float inv_w = __fdividef(1.0f, wsel);
    float xi = (tw - csel) * inv_w;
    float hk = 6.0f * hsel * inv_sh;
    float yk = fmaf(6.0f * cysel, inv_sh, -BBOUND);
    float sk = hsel * sw * inv_sh * inv_w;
    float om = 1.0f - xi;
    float xiom = xi * om;
    float denom = sk + (dk1 + dk - 2.0f * sk) * xiom;
    float y = yk + hk * __fdividef(sk * xi * xi + dk * xiom, denom);
    float num = dk1 * xi * xi + 2.0f * sk * xiom + dk * om * om;
    float ldet = __logf(__fdividef(sk * sk * num, denom * denom));

    z = inside ? y : uu;
    return inside ? ldet : 0.0f;
}

__global__ void __launch_bounds__(TPB, 3) nsf_kernel(
    const float* __restrict__ x,
    const float* __restrict__ w0, const float* __restrict__ b0,
    const float* __restrict__ w1, const float* __restrict__ b1,
    const float* __restrict__ ww, const float* __restrict__ bw,
    const float* __restrict__ wh, const float* __restrict__ bh,
    const float* __restrict__ wd, const float* __restrict__ bd,
    float* __restrict__ out, int n, int has_ld) {
    extern __shared__ float sm[];
    int tid = threadIdx.x;

    for (int i = tid; i < SMEM_FLOATS; i += TPB) sm[i] = 0.0f;
    __syncthreads();

    for (int i = tid; i < 8 * HIDN; i += TPB) {
        int k = i / HIDN, j = i % HIDN;
        sm[OFF_W0T + j * 8 + k] = w0[i];
    }
    for (int i = tid; i < HIDN; i += TPB) {
        sm[OFF_B0 + i] = b0[i];
        sm[OFF_B1 + i] = b1[i];
    }
    for (int i = tid; i < HIDN * HIDN; i += TPB) {
        int k = i / HIDN, j = i % HIDN;
        sm[OFF_W1T + j * PAD + k] = w1[i];
    }
    for (int i = tid; i < HIDN * 80; i += TPB) {
        int j = i / 80, o = i % 80;
        sm[OFF_WWT + o * PAD + j] = 6.0f * ww[i];
        sm[OFF_WHT + o * PAD + j] = 6.0f * wh[i];
    }
    for (int i = tid; i < 80; i += TPB) {
        sm[OFF_BW + i] = 6.0f * bw[i];
        sm[OFF_BH + i] = 6.0f * bh[i];
    }
    for (int i = tid; i < HIDN * 72; i += TPB) {
        int j = i / 72, o = i % 72;
        sm[OFF_WDT + o * PAD + j] = wd[i];
    }
    for (int i = tid; i < 72; i += TPB) sm[OFF_BD + i] = bd[i];
    __syncthreads();

    int half = (n + 1) >> 1;
    int r0 = blockIdx.x * TPB + tid;
    int r1 = r0 + half;
    bool v0 = (r0 < n);
    bool v1 = (r1 < n);
    float ld_acc = 0.0f;

    if (v0) {
        const float* xr0 = x + (size_t)r0 * 16;
        const float* xr1 = x + (size_t)r1 * 16;
        float* or0 = out + (size_t)r0 * 16;
        float* or1 = out + (size_t)r1 * 16;

        // row0 passthrough + MLP
        float g0[PAD], g1[PAD];
        {
            float4 a = reinterpret_cast<const float4*>(xr0)[0];
            float4 b = reinterpret_cast<const float4*>(xr0)[1];
            reinterpret_cast<float4*>(or0)[0] = a;
            reinterpret_cast<float4*>(or0)[1] = b;
            float zd[8] = {a.x, a.y, a.z, a.w, b.x, b.y, b.z, b.w};
            mlp_row(sm, zd, g0);
        }
        if (v1) {
            float4 a = reinterpret_cast<const float4*>(xr1)[0];
            float4 b = reinterpret_cast<const float4*>(xr1)[1];
            reinterpret_cast<float4*>(or1)[0] = a;
            reinterpret_cast<float4*>(or1)[1] = b;
            float zd[8] = {a.x, a.y, a.z, a.w, b.x, b.y, b.z, b.w};
            mlp_row(sm, zd, g1);
        } else {
#pragma unroll
            for (int j = 0; j < PAD; j++) g1[j] = 0.f;
        }

        float zst0 = 0.f, zst1 = 0.f;
#pragma unroll 1
        for (int dd = 0; dd < TDN; dd++) {
            float ew0[KB], ew1[KB], eh0[KB], eh1[KB];
            float sw0 = 0.f, sw1 = 0.f, sh0 = 0.f, sh1 = 0.f;
#pragma unroll
            for (int kk = 0; kk < KB; kk++) {
                int o = dd * KB + kk;
                float t0, t1;
                dot52x2(g0, g1, &sm[OFF_WWT + o * PAD], t0, t1);
                float bwo = sm[OFF_BW + o];
                ew0[kk] = __expf(t0 + bwo); sw0 += ew0[kk];
                ew1[kk] = __expf(t1 + bwo); sw1 += ew1[kk];
                dot52x2(g0, g1, &sm[OFF_WHT + o * PAD], t0, t1);
                float bho = sm[OFF_BH + o];
                eh0[kk] = __expf(t0 + bho); sh0 += eh0[kk];
                eh1[kk] = __expf(t1 + bho); sh1 += eh1[kk];
            }
            float dv0[KB - 1], dv1[KB - 1];
#pragma unroll
            for (int kk = 0; kk < KB - 1; kk++) {
                int o = dd * (KB - 1) + kk;
                float t0, t1;
                dot52x2(g0, g1, &sm[OFF_WDT + o * PAD], t0, t1);
                float bdo = sm[OFF_BD + o];
                dv0[kk] = fsoftplus(t0 + bdo);
                dv1[kk] = fsoftplus(t1 + bdo);
            }

            float z0, z1;
            ld_acc += spline_eval(xr0[8 + dd], ew0, eh0, dv0, sw0, sh0, z0);
            float l1c = spline_eval(xr1[8 + dd], ew1, eh1, dv1, sw1, sh1, z1);
            if (v1) ld_acc += l1c;

            if (dd & 1) {
                reinterpret_cast<float2*>(or0)[4 + (dd >> 1)] = make_float2(zst0, z0);
                if (v1)
                    reinterpret_cast<float2*>(or1)[4 + (dd >> 1)] = make_float2(zst1, z1);
            } else {
                zst0 = z0;
                zst1 = z1;
            }
        }
    }

    // block reduce logdet -> per-block partial
#pragma unroll
    for (int off = 16; off > 0; off >>= 1)
        ld_acc += __shfl_down_sync(0xffffffffu, ld_acc, off);
    __shared__ float s_red[TPB / 32];
    __shared__ bool s_last;
    if ((tid & 31) == 0) s_red[tid >> 5] = ld_acc;
    __syncthreads();
    if (tid == 0) {
        float t = 0.f;
#pragma unroll
        for (int i = 0; i < TPB / 32; i++) t += s_red[i];
        g_partial[blockIdx.x] = t;
        __threadfence();
        unsigned int done = atomicAdd(&g_count, 1u);
        s_last = (done == gridDim.x - 1);
    }
    __syncthreads();

    if (s_last) {
        __threadfence();
        int nb = gridDim.x;
        double acc = 0.0;
        for (int i = tid; i < nb; i += TPB) acc += (double)g_partial[i];
#pragma unroll
        for (int off = 16; off > 0; off >>= 1)
            acc += __shfl_down_sync(0xffffffffu, acc, off);
        __shared__ double s_dred[TPB / 32];
        if ((tid & 31) == 0) s_dred[tid >> 5] = acc;
        __syncthreads();
        if (tid == 0) {
            double t = 0.0;
#pragma unroll
            for (int i = 0; i < TPB / 32; i++) t += s_dred[i];
            if (has_ld) out[(size_t)n * 16] = (float)t;
            g_count = 0;
        }
    }
}

extern "C" void kernel_launch(void* const* d_in, const int* in_sizes, int n_in,
                              void* d_out, int out_size) {
    const float* x  = (const float*)d_in[0];
    const float* w0 = (const float*)d_in[1];
    const float* b0 = (const float*)d_in[2];
    const float* w1 = (const float*)d_in[3];
    const float* b1 = (const float*)d_in[4];
    const float* ww = (const float*)d_in[5];
    const float* bw = (const float*)d_in[6];
    const float* wh = (const float*)d_in[7];
    const float* bh = (const float*)d_in[8];
    const float* wd = (const float*)d_in[9];
    const float* bd = (const float*)d_in[10];
    float* out = (float*)d_out;

    int n = in_sizes[0] / 16;
    int half = (n + 1) >> 1;
    int nblocks = (half + TPB - 1) / TPB;
    int has_ld = (out_size > n * 16) ? 1 : 0;

    cudaFuncSetAttribute(nsf_kernel, cudaFuncAttributeMaxDynamicSharedMemorySize,
                         SMEM_BYTES);

    nsf_kernel<<<nblocks, TPB, SMEM_BYTES>>>(
        x, w0, b0, w1, b1, ww, bw, wh, bh, wd, bd, out, n, has_ld);
}

// round 6
// speedup vs baseline: 2.0981x; 2.0981x over previous
#include <cuda_runtime.h>
#include <cuda_bf16.h>
#include <cstdint>

#define TPB 256
#define HIDN 50
#define KB 10
#define TDN 8
#define BBOUND 3.0f
#define MAXBLK 8192

// GEMM geometry
#define NCOLS 232          // 8 dims x 29 heads
#define KTOT 160           // [ghi(50), glo(50), ghi(50), 0(10)]
#define KSTEPS 10
#define ASTRIDE_E 168      // elements per A/B row (pad for ldmatrix conflicts)
#define ASTRIDE_B 336      // bytes
#define DSTRIDE 236        // floats per D-stage row

// smem byte offsets
#define SB_MLPB 0                      // 3360 floats = 13440 B
#define SB_A    13440                  // 256*336 = 86016
#define SB_B    99456                  // 232*336 = 77952
#define SB_D    177408                 // 32*236*4 = 30208
#define SB_U    207616                 // 256*8*4 = 8192
#define SB_RED  215808                 // 32 B floats
#define SB_DRED 215840                 // 64 B doubles
#define SMEM_BYTES 215936

// MLP blob float offsets
#define MW0T 0
#define MB0  400
#define MW1T 452
#define MB1  3052
#define MBW  3104
#define MBH  3184
#define MBD  3264
#define MLP_FLOATS 3360

#define B_BYTES (NCOLS * ASTRIDE_E * 2)   // 77952

__device__ uint4 g_bblob[B_BYTES / 16];
__device__ uint4 g_mblob[MLP_FLOATS / 4];
__device__ float g_partial[MAXBLK];
__device__ unsigned int g_count = 0;

// ---------------- mma / ldmatrix (baseline sm_80+ PTX, works on sm_103) ----
__device__ __forceinline__ uint32_t smem_to_u32(const void* p) {
    uint32_t a;
    asm("{ .reg .u64 t; cvta.to.shared.u64 t, %1; cvt.u32.u64 %0, t; }"
        : "=r"(a) : "l"(p));
    return a;
}
#define LDSM_X4(r, addr) \
    asm volatile("ldmatrix.sync.aligned.m8n8.x4.shared.b16 {%0,%1,%2,%3}, [%4];" \
                 : "=r"((r)[0]), "=r"((r)[1]), "=r"((r)[2]), "=r"((r)[3]) \
                 : "r"(addr))
#define LDSM_X2(r0, r1, addr) \
    asm volatile("ldmatrix.sync.aligned.m8n8.x2.shared.b16 {%0,%1}, [%2];" \
                 : "=r"(r0), "=r"(r1) : "r"(addr))
#define MMA16816(c, a, b0, b1) \
    asm volatile("mma.sync.aligned.m16n8k16.row.col.f32.bf16.bf16.f32 " \
                 "{%0,%1,%2,%3}, {%4,%5,%6,%7}, {%8,%9}, {%0,%1,%2,%3};" \
                 : "+f"((c)[0]), "+f"((c)[1]), "+f"((c)[2]), "+f"((c)[3]) \
                 : "r"((a)[0]), "r"((a)[1]), "r"((a)[2]), "r"((a)[3]), \
                   "r"(b0), "r"(b1))

// ---------------- math helpers ----------------
__device__ __forceinline__ float ftanh(float v) {
    float e = __expf(2.0f * v);
    return 1.0f - __fdividef(2.0f, e + 1.0f);
}
__device__ __forceinline__ float fsoftplus(float v) {
    return __logf(1.0f + __expf(v));
}
__device__ __forceinline__ float bhi(float v) {
    return __bfloat162float(__float2bfloat16(v));
}
__device__ __forceinline__ uint32_t pk_bf(float a, float b) {
    __nv_bfloat162 t = __floats2bfloat162_rn(a, b);
    return *reinterpret_cast<uint32_t*>(&t);
}

__device__ __forceinline__ float dot52(const float* __restrict__ h,
                                       const float* __restrict__ w) {
    float a0 = 0.f, a1 = 0.f, a2 = 0.f, a3 = 0.f;
#pragma unroll
    for (int q = 0; q < 13; q++) {
        float4 w4 = reinterpret_cast<const float4*>(w)[q];
        a0 = fmaf(h[4 * q + 0], w4.x, a0);
        a1 = fmaf(h[4 * q + 1], w4.y, a1);
        a2 = fmaf(h[4 * q + 2], w4.z, a2);
        a3 = fmaf(h[4 * q + 3], w4.w, a3);
    }
    return (a0 + a1) + (a2 + a3);
}

// spline for one dim given exp'd logits + derivatives (validated in R3)
__device__ __forceinline__ float spline_eval(float uu, const float* __restrict__ ew,
                                             const float* __restrict__ eh,
                                             const float* __restrict__ dv,
                                             float sw, float sh, float& z) {
    bool inside = (uu > -BBOUND) && (uu < BBOUND);
    float uc = fminf(fmaxf(uu, -BBOUND), BBOUND);

    float tw = (uc + BBOUND) * sw * (1.0f / 6.0f);
    float cw = 0.f, cy = 0.f;
    float csel = 0.f, cysel = 0.f;
    float wsel = ew[0], hsel = eh[0];
    float dk = 1.0f, dk1 = dv[0];
#pragma unroll
    for (int kk = 1; kk < KB; kk++) {
        cw += ew[kk - 1];
        cy += eh[kk - 1];
        if (cw <= tw) {
            csel = cw; cysel = cy;
            wsel = ew[kk]; hsel = eh[kk];
            dk = dv[kk - 1];
            dk1 = (kk == KB - 1) ? 1.0f : dv[kk];
        }
    }
    float inv_sh = __fdividef(1.0f, sh);
    float inv_w = __fdividef(1.0f, wsel);
    float xi = (tw - csel) * inv_w;
    float hk = 6.0f * hsel * inv_sh;
    float yk = fmaf(6.0f * cysel, inv_sh, -BBOUND);
    float sk = hsel * sw * inv_sh * inv_w;
    float om = 1.0f - xi;
    float xiom = xi * om;
    float denom = sk + (dk1 + dk - 2.0f * sk) * xiom;
    float y = yk + hk * __fdividef(sk * xi * xi + dk * xiom, denom);
    float num = dk1 * xi * xi + 2.0f * sk * xiom + dk * om * om;
    float ldet = __logf(__fdividef(sk * sk * num, denom * denom));
    z = inside ? y : uu;
    return inside ? ldet : 0.0f;
}

// ---------------- prep kernel ----------------
__global__ void prep_kernel(
    const float* __restrict__ w0, const float* __restrict__ b0,
    const float* __restrict__ w1, const float* __restrict__ b1,
    const float* __restrict__ ww, const float* __restrict__ bw,
    const float* __restrict__ wh, const float* __restrict__ bh,
    const float* __restrict__ wd, const float* __restrict__ bd) {
    int i = blockIdx.x * blockDim.x + threadIdx.x;
    int stride = gridDim.x * blockDim.x;

    // B' blob: [n=232][k=168] bf16, n-major, k-blocks [Whi, Whi, Wlo, 0]
    uint16_t* bb = reinterpret_cast<uint16_t*>(g_bblob);
    for (int idx = i; idx < NCOLS * ASTRIDE_E; idx += stride) {
        int nn = idx / ASTRIDE_E, k = idx % ASTRIDE_E;
        uint16_t bits = 0;
        if (k < 150) {
            int blk = (k < 50) ? 0 : ((k < 100) ? 1 : 2);
            int c = k - 50 * blk;
            int dd = nn / 29, j = nn % 29;
            float w;
            if (j < 10) w = 6.0f * ww[c * 80 + dd * 10 + j];
            else if (j < 20) w = 6.0f * wh[c * 80 + dd * 10 + (j - 10)];
            else w = wd[c * 72 + dd * 9 + (j - 20)];
            __nv_bfloat16 hb = __float2bfloat16(w);
            if (blk < 2) bits = __bfloat16_as_ushort(hb);
            else {
                __nv_bfloat16 lb = __float2bfloat16(w - __bfloat162float(hb));
                bits = __bfloat16_as_ushort(lb);
            }
        }
        bb[idx] = bits;
    }

    float* mf = reinterpret_cast<float*>(g_mblob);
    for (int idx = i; idx < MLP_FLOATS; idx += stride) {
        float v = 0.0f;
        if (idx < 400) { int j = idx >> 3, k = idx & 7; v = w0[k * 50 + j]; }
        else if (idx < 452) { int t = idx - 400; v = (t < 50) ? b0[t] : 0.f; }
        else if (idx < 3052) {
            int t = idx - 452; int j = t / 52, k = t % 52;
            v = (k < 50) ? w1[k * 50 + j] : 0.f;
        }
        else if (idx < 3104) { int t = idx - 3052; v = (t < 50) ? b1[t] : 0.f; }
        else if (idx < 3184) v = 6.0f * bw[idx - 3104];
        else if (idx < 3264) v = 6.0f * bh[idx - 3184];
        else if (idx < 3336) v = bd[idx - 3264];
        mf[idx] = v;
    }
}

// ---------------- main fused kernel ----------------
__global__ void __launch_bounds__(TPB, 1) nsf_kernel(
    const float* __restrict__ x, float* __restrict__ out, int n, int has_ld) {
    extern __shared__ char smem[];
    uint32_t smem_base = smem_to_u32(smem);
    int tid = threadIdx.x;
    int wid = tid >> 5;
    int lane = tid & 31;

    // stage weight blobs
    {
        uint4* sM = reinterpret_cast<uint4*>(smem + SB_MLPB);
        for (int i = tid; i < MLP_FLOATS / 4; i += TPB) sM[i] = g_mblob[i];
        uint4* sB = reinterpret_cast<uint4*>(smem + SB_B);
        for (int i = tid; i < B_BYTES / 16; i += TPB) sB[i] = g_bblob[i];
    }
    __syncthreads();
    const float* smf = reinterpret_cast<const float*>(smem + SB_MLPB);

    int base = blockIdx.x * TPB;
    int row = base + tid;
    bool valid = (row < n);
    int rr = valid ? row : (n - 1);

    // load x row; passthrough + stash u in smem
    {
        const float4* xr = reinterpret_cast<const float4*>(x + (size_t)rr * 16);
        float4 x0 = xr[0], x1 = xr[1], x2 = xr[2], x3 = xr[3];
        if (valid) {
            float4* ov = reinterpret_cast<float4*>(out + (size_t)rr * 16);
            ov[0] = x0;
            ov[1] = x1;
        }
        float4* su = reinterpret_cast<float4*>(smem + SB_U) + tid * 2;
        su[0] = x2;
        su[1] = x3;

        // MLP layer 0 + 1 -> stream split-bf16 into A
        float zd[8] = {x0.x, x0.y, x0.z, x0.w, x1.x, x1.y, x1.z, x1.w};
        float h[52];
#pragma unroll
        for (int j = 0; j < HIDN; j++) {
            const float4* wv = reinterpret_cast<const float4*>(&smf[MW0T + j * 8]);
            float4 a = wv[0], b = wv[1];
            float acc = smf[MB0 + j];
            acc = fmaf(zd[0], a.x, acc);
            acc = fmaf(zd[1], a.y, acc);
            acc = fmaf(zd[2], a.z, acc);
            acc = fmaf(zd[3], a.w, acc);
            acc = fmaf(zd[4], b.x, acc);
            acc = fmaf(zd[5], b.y, acc);
            acc = fmaf(zd[6], b.z, acc);
            acc = fmaf(zd[7], b.w, acc);
            h[j] = ftanh(acc);
        }
        h[50] = 0.f; h[51] = 0.f;

        uint32_t* arow = reinterpret_cast<uint32_t*>(smem + SB_A + tid * ASTRIDE_B);
#pragma unroll
        for (int jp = 0; jp < 25; jp++) {
            float g0 = ftanh(dot52(h, &smf[MW1T + (2 * jp) * 52]) + smf[MB1 + 2 * jp]);
            float g1 = ftanh(dot52(h, &smf[MW1T + (2 * jp + 1) * 52]) + smf[MB1 + 2 * jp + 1]);
            float h0 = bhi(g0), h1 = bhi(g1);
            uint32_t hi = pk_bf(g0, g1);
            uint32_t lo = pk_bf(g0 - h0, g1 - h1);
            arow[jp] = hi;          // k = 2jp..2jp+1
            arow[25 + jp] = lo;     // k = 50+2jp
            arow[50 + jp] = hi;     // k = 100+2jp
        }
#pragma unroll
        for (int jp = 75; jp < 80; jp++) arow[jp] = 0u;  // k = 150..159
    }
    __syncthreads();

    // GEMM + epilogue, 8 iterations of 2 m-tiles (32 rows)
    float ld_acc = 0.0f;
    int j4 = wid & 3;
    int s0 = (j4 == 0) ? 0 : ((j4 == 1) ? 8 : ((j4 == 2) ? 15 : 22));
    int s1 = (j4 == 0) ? 8 : ((j4 == 1) ? 15 : ((j4 == 2) ? 22 : 29));
    int l16 = lane & 15;
    uint32_t bconst = smem_base + SB_B + (uint32_t)(l16 & 7) * ASTRIDE_B +
                      (uint32_t)((l16 >> 3) * 16);
    const float* dstage = reinterpret_cast<const float*>(smem + SB_D);
    float* dstagew = reinterpret_cast<float*>(smem + SB_D);
    const float* su = reinterpret_cast<const float*>(smem + SB_U);

#pragma unroll 1
    for (int it = 0; it < 8; it++) {
        int mt = 2 * it + (wid >> 2);
        // preload A fragments for this warp's m-tile (all 10 k-steps)
        uint32_t af[10][4];
        {
            uint32_t abase = smem_base + SB_A +
                             (uint32_t)(mt * 16 + (lane & 15)) * ASTRIDE_B +
                             (uint32_t)((lane >> 4) * 16);
#pragma unroll
            for (int s = 0; s < KSTEPS; s++) LDSM_X4(af[s], abase + s * 32);
        }
        int drow = ((mt & 1) << 4) + (lane >> 2);
        int dcol0 = (lane & 3) << 1;

#pragma unroll 1
        for (int nt = s0; nt < s1; nt += 2) {
            uint32_t ba = bconst + (uint32_t)nt * (8 * ASTRIDE_B);
            float c0[4] = {0.f, 0.f, 0.f, 0.f};
            if (nt + 1 < s1) {
                float c1[4] = {0.f, 0.f, 0.f, 0.f};
#pragma unroll
                for (int s = 0; s < KSTEPS; s++) {
                    uint32_t b0, b1, e0, e1;
                    LDSM_X2(b0, b1, ba + s * 32);
                    LDSM_X2(e0, e1, ba + 8 * ASTRIDE_B + s * 32);
                    MMA16816(c0, af[s], b0, b1);
                    MMA16816(c1, af[s], e0, e1);
                }
                int dc = nt * 8 + dcol0;
                *reinterpret_cast<float2*>(dstagew + drow * DSTRIDE + dc) =
                    make_float2(c0[0], c0[1]);
                *reinterpret_cast<float2*>(dstagew + (drow + 8) * DSTRIDE + dc) =
                    make_float2(c0[2], c0[3]);
                *reinterpret_cast<float2*>(dstagew + drow * DSTRIDE + dc + 8) =
                    make_float2(c1[0], c1[1]);
                *reinterpret_cast<float2*>(dstagew + (drow + 8) * DSTRIDE + dc + 8) =
                    make_float2(c1[2], c1[3]);
            } else {
#pragma unroll
                for (int s = 0; s < KSTEPS; s++) {
                    uint32_t b0, b1;
                    LDSM_X2(b0, b1, ba + s * 32);
                    MMA16816(c0, af[s], b0, b1);
                }
                int dc = nt * 8 + dcol0;
                *reinterpret_cast<float2*>(dstagew + drow * DSTRIDE + dc) =
                    make_float2(c0[0], c0[1]);
                *reinterpret_cast<float2*>(dstagew + (drow + 8) * DSTRIDE + dc) =
                    make_float2(c0[2], c0[3]);
            }
        }
        __syncthreads();

        // epilogue: thread -> (local row, dim)
        {
            int lrow = tid >> 3;
            int dd = tid & 7;
            int grow = base + it * 32 + lrow;
            bool gvalid = (grow < n);
            const float* dr = dstage + lrow * DSTRIDE + dd * 29;

            float ew[KB], eh[KB], dv[KB - 1];
            float sw = 0.f, sh = 0.f;
#pragma unroll
            for (int j = 0; j < KB; j++) {
                ew[j] = __expf(dr[j] + smf[MBW + dd * 10 + j]);
                sw += ew[j];
                eh[j] = __expf(dr[10 + j] + smf[MBH + dd * 10 + j]);
                sh += eh[j];
            }
#pragma unroll
            for (int j = 0; j < KB - 1; j++) {
                dv[j] = fsoftplus(dr[20 + j] + smf[MBD + dd * 9 + j]);
            }
            float uu = su[it * 256 + tid];
            float z;
            float ldet = spline_eval(uu, ew, eh, dv, sw, sh, z);
            if (gvalid) {
                out[(size_t)grow * 16 + 8 + dd] = z;
                ld_acc += ldet;
            }
        }
        __syncthreads();
    }

    // logdet block reduction -> partial; last block reduces all
    float* s_red = reinterpret_cast<float*>(smem + SB_RED);
    double* s_dred = reinterpret_cast<double*>(smem + SB_DRED);
#pragma unroll
    for (int off = 16; off > 0; off >>= 1)
        ld_acc += __shfl_down_sync(0xffffffffu, ld_acc, off);
    if (lane == 0) s_red[wid] = ld_acc;
    __syncthreads();
    if (tid == 0) {
        float t = 0.f;
#pragma unroll
        for (int i = 0; i < TPB / 32; i++) t += s_red[i];
        g_partial[blockIdx.x] = t;
        __threadfence();
        unsigned int done = atomicAdd(&g_count, 1u);
        s_red[0] = (done == gridDim.x - 1) ? 1.0f : 0.0f;
    }
    __syncthreads();
    if (s_red[0] != 0.0f) {
        __threadfence();
        int nb = gridDim.x;
        double acc = 0.0;
        for (int i = tid; i < nb; i += TPB) acc += (double)g_partial[i];
#pragma unroll
        for (int off = 16; off > 0; off >>= 1)
            acc += __shfl_down_sync(0xffffffffu, acc, off);
        if (lane == 0) s_dred[wid] = acc;
        __syncthreads();
        if (tid == 0) {
            double t = 0.0;
#pragma unroll
            for (int i = 0; i < TPB / 32; i++) t += s_dred[i];
            if (has_ld) out[(size_t)n * 16] = (float)t;
            g_count = 0;
        }
    }
}

extern "C" void kernel_launch(void* const* d_in, const int* in_sizes, int n_in,
                              void* d_out, int out_size) {
    const float* x  = (const float*)d_in[0];
    const float* w0 = (const float*)d_in[1];
    const float* b0 = (const float*)d_in[2];
    const float* w1 = (const float*)d_in[3];
    const float* b1 = (const float*)d_in[4];
    const float* ww = (const float*)d_in[5];
    const float* bw = (const float*)d_in[6];
    const float* wh = (const float*)d_in[7];
    const float* bh = (const float*)d_in[8];
    const float* wd = (const float*)d_in[9];
    const float* bd = (const float*)d_in[10];
    float* out = (float*)d_out;

    int n = in_sizes[0] / 16;
    int nblocks = (n + TPB - 1) / TPB;
    int has_ld = (out_size > n * 16) ? 1 : 0;

    cudaFuncSetAttribute(nsf_kernel, cudaFuncAttributeMaxDynamicSharedMemorySize,
                         SMEM_BYTES);

    prep_kernel<<<94, 512>>>(w0, b0, w1, b1, ww, bw, wh, bh, wd, bd);
    nsf_kernel<<<nblocks, TPB, SMEM_BYTES>>>(x, out, n, has_ld);
}

// round 7
// speedup vs baseline: 3.0788x; 1.4674x over previous
#include <cuda_runtime.h>
#include <cuda_bf16.h>
#include <cstdint>

#define TPB 256
#define HIDN 50
#define KB 10
#define TDN 8
#define BBOUND 3.0f
#define MAXBLK 8192

#define NCOLS 232
#define NT 29              // n-tiles of 8
#define ASTR 272           // bytes per A row (68 words: 4-bank stagger, 16B aligned)
#define DSTRIDE 236

// smem byte offsets
#define SB_MLPB 0                       // 13440
#define SB_A    13440                   // 256*272 = 69632
#define SB_D    83072                   // 32*236*4 = 30208
#define SB_RED  113280
#define SB_DRED 113312
#define SMEM_BYTES 113408               // x2 CTAs = 221.5 KiB <= 227 KiB

// MLP blob float offsets
#define MW0T 0
#define MB0  400
#define MW1T 452
#define MB1  3052
#define MBW  3104
#define MBH  3184
#define MBD  3264
#define MLP_FLOATS 3360

__device__ uint2 g_bfrag[NT * 8 * 32];       // fragment-ordered B' (59392 B)
__device__ uint4 g_mblob[MLP_FLOATS / 4];
__device__ float g_partial[MAXBLK];
__device__ unsigned int g_count = 0;

// ---------------- mma / ldmatrix ----------------
__device__ __forceinline__ uint32_t smem_to_u32(const void* p) {
    uint32_t a;
    asm("{ .reg .u64 t; cvta.to.shared.u64 t, %1; cvt.u32.u64 %0, t; }"
        : "=r"(a) : "l"(p));
    return a;
}
#define LDSM_X4(r, addr) \
    asm volatile("ldmatrix.sync.aligned.m8n8.x4.shared.b16 {%0,%1,%2,%3}, [%4];" \
                 : "=r"((r)[0]), "=r"((r)[1]), "=r"((r)[2]), "=r"((r)[3]) \
                 : "r"(addr))
#define MMA16816(c, a, b0, b1) \
    asm volatile("mma.sync.aligned.m16n8k16.row.col.f32.bf16.bf16.f32 " \
                 "{%0,%1,%2,%3}, {%4,%5,%6,%7}, {%8,%9}, {%0,%1,%2,%3};" \
                 : "+f"((c)[0]), "+f"((c)[1]), "+f"((c)[2]), "+f"((c)[3]) \
                 : "r"((a)[0]), "r"((a)[1]), "r"((a)[2]), "r"((a)[3]), \
                   "r"(b0), "r"(b1))

// ---------------- math helpers ----------------
__device__ __forceinline__ float ftanh(float v) {
    float e = __expf(2.0f * v);
    return 1.0f - __fdividef(2.0f, e + 1.0f);
}
__device__ __forceinline__ float fsoftplus(float v) {
    return __logf(1.0f + __expf(v));
}
__device__ __forceinline__ float bhi(float v) {
    return __bfloat162float(__float2bfloat16(v));
}
__device__ __forceinline__ uint32_t pk_bf(float a, float b) {
    __nv_bfloat162 t = __floats2bfloat162_rn(a, b);
    return *reinterpret_cast<uint32_t*>(&t);
}

__device__ __forceinline__ float dot52(const float* __restrict__ h,
                                       const float* __restrict__ w) {
    float a0 = 0.f, a1 = 0.f, a2 = 0.f, a3 = 0.f;
#pragma unroll
    for (int q = 0; q < 13; q++) {
        float4 w4 = reinterpret_cast<const float4*>(w)[q];
        a0 = fmaf(h[4 * q + 0], w4.x, a0);
        a1 = fmaf(h[4 * q + 1], w4.y, a1);
        a2 = fmaf(h[4 * q + 2], w4.z, a2);
        a3 = fmaf(h[4 * q + 3], w4.w, a3);
    }
    return (a0 + a1) + (a2 + a3);
}

__device__ __forceinline__ float spline_eval(float uu, const float* __restrict__ ew,
                                             const float* __restrict__ eh,
                                             const float* __restrict__ dv,
                                             float sw, float sh, float& z) {
    bool inside = (uu > -BBOUND) && (uu < BBOUND);
    float uc = fminf(fmaxf(uu, -BBOUND), BBOUND);

    float tw = (uc + BBOUND) * sw * (1.0f / 6.0f);
    float cw = 0.f, cy = 0.f;
    float csel = 0.f, cysel = 0.f;
    float wsel = ew[0], hsel = eh[0];
    float dk = 1.0f, dk1 = dv[0];
#pragma unroll
    for (int kk = 1; kk < KB; kk++) {
        cw += ew[kk - 1];
        cy += eh[kk - 1];
        if (cw <= tw) {
            csel = cw; cysel = cy;
            wsel = ew[kk]; hsel = eh[kk];
            dk = dv[kk - 1];
            dk1 = (kk == KB - 1) ? 1.0f : dv[kk];
        }
    }
    float inv_sh = __fdividef(1.0f, sh);
    float inv_w = __fdividef(1.0f, wsel);
    float xi = (tw - csel) * inv_w;
    float hk = 6.0f * hsel * inv_sh;
    float yk = fmaf(6.0f * cysel, inv_sh, -BBOUND);
    float sk = hsel * sw * inv_sh * inv_w;
    float om = 1.0f - xi;
    float xiom = xi * om;
    float denom = sk + (dk1 + dk - 2.0f * sk) * xiom;
    float y = yk + hk * __fdividef(sk * xi * xi + dk * xiom, denom);
    float num = dk1 * xi * xi + 2.0f * sk * xiom + dk * om * om;
    float ldet = __logf(__fdividef(sk * sk * num, denom * denom));
    z = inside ? y : uu;
    return inside ? ldet : 0.0f;
}

// ---------------- prep kernel ----------------
__device__ __forceinline__ float head_w(const float* ww, const float* wh,
                                        const float* wd, int c, int n) {
    // c = k within 64-block (0..63), n = output column (0..231)
    if (c >= 50) return 0.0f;
    int dd = n / 29, j = n % 29;
    if (j < 10) return 6.0f * ww[c * 80 + dd * 10 + j];
    if (j < 20) return 6.0f * wh[c * 80 + dd * 10 + (j - 10)];
    return wd[c * 72 + dd * 9 + (j - 20)];
}

__global__ void prep_kernel(
    const float* __restrict__ w0, const float* __restrict__ b0,
    const float* __restrict__ w1, const float* __restrict__ b1,
    const float* __restrict__ ww, const float* __restrict__ bw,
    const float* __restrict__ wh, const float* __restrict__ bh,
    const float* __restrict__ wd, const float* __restrict__ bd) {
    int i = blockIdx.x * blockDim.x + threadIdx.x;
    int stride = gridDim.x * blockDim.x;

    // fragment-ordered B': ustep 0..3 = Whi(k 0..63), 4..7 = Wlo(k 0..63)
    for (int idx = i; idx < NT * 8 * 32; idx += stride) {
        int l = idx & 31;
        int s = (idx >> 5) & 7;
        int nt = idx >> 8;
        int n = nt * 8 + (l >> 2);
        int blk = s >> 2;
        int kb = (s & 3) * 16 + 2 * (l & 3);
        float w00 = head_w(ww, wh, wd, kb, n);
        float w01 = head_w(ww, wh, wd, kb + 1, n);
        float w10 = head_w(ww, wh, wd, kb + 8, n);
        float w11 = head_w(ww, wh, wd, kb + 9, n);
        if (blk) {
            w00 -= bhi(w00); w01 -= bhi(w01);
            w10 -= bhi(w10); w11 -= bhi(w11);
        }
        g_bfrag[idx] = make_uint2(pk_bf(w00, w01), pk_bf(w10, w11));
    }

    float* mf = reinterpret_cast<float*>(g_mblob);
    for (int idx = i; idx < MLP_FLOATS; idx += stride) {
        float v = 0.0f;
        if (idx < 400) { int j = idx >> 3, k = idx & 7; v = w0[k * 50 + j]; }
        else if (idx < 452) { int t = idx - 400; v = (t < 50) ? b0[t] : 0.f; }
        else if (idx < 3052) {
            int t = idx - 452; int j = t / 52, k = t % 52;
            v = (k < 50) ? w1[k * 50 + j] : 0.f;
        }
        else if (idx < 3104) { int t = idx - 3052; v = (t < 50) ? b1[t] : 0.f; }
        else if (idx < 3184) v = 6.0f * bw[idx - 3104];
        else if (idx < 3264) v = 6.0f * bh[idx - 3184];
        else if (idx < 3336) v = bd[idx - 3264];
        mf[idx] = v;
    }
}

// ---------------- main fused kernel ----------------
__global__ void __launch_bounds__(TPB, 2) nsf_kernel(
    const float* __restrict__ x, float* __restrict__ out, int n, int has_ld) {
    extern __shared__ char smem[];
    uint32_t smem_base = smem_to_u32(smem);
    int tid = threadIdx.x;
    int wid = tid >> 5;
    int lane = tid & 31;

    // stage MLP blob
    {
        uint4* sM = reinterpret_cast<uint4*>(smem + SB_MLPB);
        for (int i = tid; i < MLP_FLOATS / 4; i += TPB) sM[i] = g_mblob[i];
    }
    __syncthreads();
    const float* smf = reinterpret_cast<const float*>(smem + SB_MLPB);

    int base = blockIdx.x * TPB;
    int row = base + tid;
    bool valid = (row < n);
    int rr = valid ? row : (n - 1);

    // MLP phase: x -> h -> g, write split-bf16 A [hi(64) | lo(64)]
    {
        const float4* xr = reinterpret_cast<const float4*>(x + (size_t)rr * 16);
        float4 x0 = xr[0], x1 = xr[1];
        if (valid) {
            float4* ov = reinterpret_cast<float4*>(out + (size_t)rr * 16);
            ov[0] = x0;
            ov[1] = x1;
        }
        float zd[8] = {x0.x, x0.y, x0.z, x0.w, x1.x, x1.y, x1.z, x1.w};
        float h[52];
#pragma unroll
        for (int j = 0; j < HIDN; j++) {
            const float4* wv = reinterpret_cast<const float4*>(&smf[MW0T + j * 8]);
            float4 a = wv[0], b = wv[1];
            float acc = smf[MB0 + j];
            acc = fmaf(zd[0], a.x, acc);
            acc = fmaf(zd[1], a.y, acc);
            acc = fmaf(zd[2], a.z, acc);
            acc = fmaf(zd[3], a.w, acc);
            acc = fmaf(zd[4], b.x, acc);
            acc = fmaf(zd[5], b.y, acc);
            acc = fmaf(zd[6], b.z, acc);
            acc = fmaf(zd[7], b.w, acc);
            h[j] = ftanh(acc);
        }
        h[50] = 0.f; h[51] = 0.f;

        uint32_t* arow = reinterpret_cast<uint32_t*>(smem + SB_A + tid * ASTR);
#pragma unroll
        for (int jp = 0; jp < 25; jp++) {
            float g0 = ftanh(dot52(h, &smf[MW1T + (2 * jp) * 52]) + smf[MB1 + 2 * jp]);
            float g1 = ftanh(dot52(h, &smf[MW1T + (2 * jp + 1) * 52]) + smf[MB1 + 2 * jp + 1]);
            arow[jp] = pk_bf(g0, g1);
            arow[32 + jp] = pk_bf(g0 - bhi(g0), g1 - bhi(g1));
        }
#pragma unroll
        for (int jp = 25; jp < 32; jp++) {
            arow[jp] = 0u;
            arow[32 + jp] = 0u;
        }
    }

    // load this warp's persistent B fragments from global (L2-hot)
    int cnt = (wid < 5) ? 4 : 3;
    uint2 Bf[4][8];
#pragma unroll
    for (int i = 0; i < 4; i++) {
        if (i < cnt) {
            int nt = wid + 8 * i;
#pragma unroll
            for (int s = 0; s < 8; s++)
                Bf[i][s] = g_bfrag[(nt * 8 + s) * 32 + lane];
        }
    }
    __syncthreads();

    float ld_acc = 0.0f;
    float* dst = reinterpret_cast<float*>(smem + SB_D);
    int drow = lane >> 2, dcol0 = (lane & 3) << 1;

#pragma unroll 1
    for (int it = 0; it < 8; it++) {
#pragma unroll
        for (int half = 0; half < 2; half++) {
            int mt = 2 * it + half;
            uint32_t abase = smem_base + SB_A +
                             (uint32_t)(mt * 16 + (lane & 15)) * ASTR +
                             (uint32_t)((lane >> 4) * 16);
            float D0[4][4];
#pragma unroll
            for (int i = 0; i < 4; i++)
#pragma unroll
                for (int q = 0; q < 4; q++) D0[i][q] = 0.f;

#pragma unroll
            for (int s = 0; s < 4; s++) {
                uint32_t Ah[4], Al[4];
                LDSM_X4(Ah, abase + s * 32);
                LDSM_X4(Al, abase + 128 + s * 32);
#pragma unroll
                for (int i = 0; i < 4; i++) {
                    if (i < cnt) {
                        MMA16816(D0[i], Ah, Bf[i][s].x, Bf[i][s].y);      // ghi*Whi
                        MMA16816(D0[i], Al, Bf[i][s].x, Bf[i][s].y);      // glo*Whi
                        MMA16816(D0[i], Ah, Bf[i][4 + s].x, Bf[i][4 + s].y); // ghi*Wlo
                    }
                }
            }
#pragma unroll
            for (int i = 0; i < 4; i++) {
                if (i < cnt) {
                    int dc = (wid + 8 * i) * 8 + dcol0;
                    int dr = half * 16 + drow;
                    *reinterpret_cast<float2*>(dst + dr * DSTRIDE + dc) =
                        make_float2(D0[i][0], D0[i][1]);
                    *reinterpret_cast<float2*>(dst + (dr + 8) * DSTRIDE + dc) =
                        make_float2(D0[i][2], D0[i][3]);
                }
            }
        }
        __syncthreads();

        // epilogue: 256 threads = 32 rows x 8 dims
        {
            int lrow = tid >> 3;
            int dd = tid & 7;
            int grow = base + it * 32 + lrow;
            bool gvalid = (grow < n);
            int gr = gvalid ? grow : (n - 1);
            const float* dr = dst + lrow * DSTRIDE + dd * 29;

            float ew[KB], eh[KB], dv[KB - 1];
            float sw = 0.f, sh = 0.f;
#pragma unroll
            for (int j = 0; j < KB; j++) {
                ew[j] = __expf(dr[j] + smf[MBW + dd * 10 + j]);
                sw += ew[j];
                eh[j] = __expf(dr[10 + j] + smf[MBH + dd * 10 + j]);
                sh += eh[j];
            }
#pragma unroll
            for (int j = 0; j < KB - 1; j++) {
                dv[j] = fsoftplus(dr[20 + j] + smf[MBD + dd * 9 + j]);
            }
            float uu = __ldg(x + (size_t)gr * 16 + 8 + dd);
            float z;
            float ldet = spline_eval(uu, ew, eh, dv, sw, sh, z);
            if (gvalid) {
                out[(size_t)grow * 16 + 8 + dd] = z;
                ld_acc += ldet;
            }
        }
        __syncthreads();
    }

    // logdet reduction
    float* s_red = reinterpret_cast<float*>(smem + SB_RED);
    double* s_dred = reinterpret_cast<double*>(smem + SB_DRED);
#pragma unroll
    for (int off = 16; off > 0; off >>= 1)
        ld_acc += __shfl_down_sync(0xffffffffu, ld_acc, off);
    if (lane == 0) s_red[wid] = ld_acc;
    __syncthreads();
    if (tid == 0) {
        float t = 0.f;
#pragma unroll
        for (int i = 0; i < TPB / 32; i++) t += s_red[i];
        g_partial[blockIdx.x] = t;
        __threadfence();
        unsigned int done = atomicAdd(&g_count, 1u);
        s_red[0] = (done == gridDim.x - 1) ? 1.0f : 0.0f;
    }
    __syncthreads();
    if (s_red[0] != 0.0f) {
        __threadfence();
        int nb = gridDim.x;
        double acc = 0.0;
        for (int i = tid; i < nb; i += TPB) acc += (double)g_partial[i];
#pragma unroll
        for (int off = 16; off > 0; off >>= 1)
            acc += __shfl_down_sync(0xffffffffu, acc, off);
        if (lane == 0) s_dred[wid] = acc;
        __syncthreads();
        if (tid == 0) {
            double t = 0.0;
#pragma unroll
            for (int i = 0; i < TPB / 32; i++) t += s_dred[i];
            if (has_ld) out[(size_t)n * 16] = (float)t;
            g_count = 0;
        }
    }
}

extern "C" void kernel_launch(void* const* d_in, const int* in_sizes, int n_in,
                              void* d_out, int out_size) {
    const float* x  = (const float*)d_in[0];
    const float* w0 = (const float*)d_in[1];
    const float* b0 = (const float*)d_in[2];
    const float* w1 = (const float*)d_in[3];
    const float* b1 = (const float*)d_in[4];
    const float* ww = (const float*)d_in[5];
    const float* bw = (const float*)d_in[6];
    const float* wh = (const float*)d_in[7];
    const float* bh = (const float*)d_in[8];
    const float* wd = (const float*)d_in[9];
    const float* bd = (const float*)d_in[10];
    float* out = (float*)d_out;

    int n = in_sizes[0] / 16;
    int nblocks = (n + TPB - 1) / TPB;
    int has_ld = (out_size > n * 16) ? 1 : 0;

    cudaFuncSetAttribute(nsf_kernel, cudaFuncAttributeMaxDynamicSharedMemorySize,
                         SMEM_BYTES);

    prep_kernel<<<40, 256>>>(w0, b0, w1, b1, ww, bw, wh, bh, wd, bd);
    nsf_kernel<<<nblocks, TPB, SMEM_BYTES>>>(x, out, n, has_ld);
}

// round 8
// speedup vs baseline: 3.2747x; 1.0637x over previous
#include <cuda_runtime.h>
#include <cuda_bf16.h>
#include <cstdint>

#define TPB 256
#define HIDN 50
#define KB 10
#define TDN 8
#define BBOUND 3.0f
#define MAXBLK 8192

#define NT 29               // head n-tiles of 8 (232 cols)
#define NT1 7               // layer1 n-tiles of 8 (56 cols, 50 used)
#define ASTR 272            // bytes per A row (68 words)
#define DSTRIDE 236         // floats per D2-stage row
#define D1STRIDE 56         // floats per D1-stage row

// smem byte offsets
#define SB_MLPB 0                       // 736 floats = 2944
#define SB_A    2944                    // 256*272 = 69632
#define SB_D    72576                   // max(64*56*4=14336, 32*236*4=30208)
#define SB_RED  102784
#define SB_DRED 102816
#define SMEM_BYTES 102912               // x2 CTAs fits 227KB

// MLP blob float offsets
#define MW0T 0
#define MB0  400
#define MB1  452
#define MBW  504
#define MBH  584
#define MBD  664
#define MLP_FLOATS 736

__device__ uint2 g_bfrag[NT * 8 * 32];    // head weights, fragment-ordered
__device__ uint2 g_b1frag[NT1 * 8 * 32];  // w1 weights, fragment-ordered
__device__ uint4 g_mblob[MLP_FLOATS / 4];
__device__ float g_partial[MAXBLK];
__device__ unsigned int g_count = 0;

// ---------------- mma / ldmatrix ----------------
__device__ __forceinline__ uint32_t smem_to_u32(const void* p) {
    uint32_t a;
    asm("{ .reg .u64 t; cvta.to.shared.u64 t, %1; cvt.u32.u64 %0, t; }"
        : "=r"(a) : "l"(p));
    return a;
}
#define LDSM_X4(r, addr) \
    asm volatile("ldmatrix.sync.aligned.m8n8.x4.shared.b16 {%0,%1,%2,%3}, [%4];" \
                 : "=r"((r)[0]), "=r"((r)[1]), "=r"((r)[2]), "=r"((r)[3]) \
                 : "r"(addr))
#define MMA16816(c, a, b0, b1) \
    asm volatile("mma.sync.aligned.m16n8k16.row.col.f32.bf16.bf16.f32 " \
                 "{%0,%1,%2,%3}, {%4,%5,%6,%7}, {%8,%9}, {%0,%1,%2,%3};" \
                 : "+f"((c)[0]), "+f"((c)[1]), "+f"((c)[2]), "+f"((c)[3]) \
                 : "r"((a)[0]), "r"((a)[1]), "r"((a)[2]), "r"((a)[3]), \
                   "r"(b0), "r"(b1))

// ---------------- math helpers ----------------
__device__ __forceinline__ float ftanh(float v) {
    float e = __expf(2.0f * v);
    return 1.0f - __fdividef(2.0f, e + 1.0f);
}
__device__ __forceinline__ float fsoftplus(float v) {
    return __logf(1.0f + __expf(v));
}
__device__ __forceinline__ float bhi(float v) {
    return __bfloat162float(__float2bfloat16(v));
}
__device__ __forceinline__ uint32_t pk_bf(float a, float b) {
    __nv_bfloat162 t = __floats2bfloat162_rn(a, b);
    return *reinterpret_cast<uint32_t*>(&t);
}

__device__ __forceinline__ float spline_eval(float uu, const float* __restrict__ ew,
                                             const float* __restrict__ eh,
                                             const float* __restrict__ dv,
                                             float sw, float sh, float& z) {
    bool inside = (uu > -BBOUND) && (uu < BBOUND);
    float uc = fminf(fmaxf(uu, -BBOUND), BBOUND);

    float tw = (uc + BBOUND) * sw * (1.0f / 6.0f);
    float cw = 0.f, cy = 0.f;
    float csel = 0.f, cysel = 0.f;
    float wsel = ew[0], hsel = eh[0];
    float dk = 1.0f, dk1 = dv[0];
#pragma unroll
    for (int kk = 1; kk < KB; kk++) {
        cw += ew[kk - 1];
        cy += eh[kk - 1];
        if (cw <= tw) {
            csel = cw; cysel = cy;
            wsel = ew[kk]; hsel = eh[kk];
            dk = dv[kk - 1];
            dk1 = (kk == KB - 1) ? 1.0f : dv[kk];
        }
    }
    float inv_sh = __fdividef(1.0f, sh);
    float inv_w = __fdividef(1.0f, wsel);
    float xi = (tw - csel) * inv_w;
    float hk = 6.0f * hsel * inv_sh;
    float yk = fmaf(6.0f * cysel, inv_sh, -BBOUND);
    float sk = hsel * sw * inv_sh * inv_w;
    float om = 1.0f - xi;
    float xiom = xi * om;
    float denom = sk + (dk1 + dk - 2.0f * sk) * xiom;
    float y = yk + hk * __fdividef(sk * xi * xi + dk * xiom, denom);
    float num = dk1 * xi * xi + 2.0f * sk * xiom + dk * om * om;
    float ldet = __logf(__fdividef(sk * sk * num, denom * denom));
    z = inside ? y : uu;
    return inside ? ldet : 0.0f;
}

// ---------------- prep kernel ----------------
__device__ __forceinline__ float head_w(const float* ww, const float* wh,
                                        const float* wd, int c, int n) {
    if (c >= 50) return 0.0f;
    int dd = n / 29, j = n % 29;
    if (j < 10) return 6.0f * ww[c * 80 + dd * 10 + j];
    if (j < 20) return 6.0f * wh[c * 80 + dd * 10 + (j - 10)];
    return wd[c * 72 + dd * 9 + (j - 20)];
}

__global__ void prep_kernel(
    const float* __restrict__ w0, const float* __restrict__ b0,
    const float* __restrict__ w1, const float* __restrict__ b1,
    const float* __restrict__ ww, const float* __restrict__ bw,
    const float* __restrict__ wh, const float* __restrict__ bh,
    const float* __restrict__ wd, const float* __restrict__ bd) {
    int i = blockIdx.x * blockDim.x + threadIdx.x;
    int stride = gridDim.x * blockDim.x;

    // head B fragments: ustep 0..3 = Whi(k 0..63), 4..7 = Wlo
    for (int idx = i; idx < NT * 8 * 32; idx += stride) {
        int l = idx & 31;
        int s = (idx >> 5) & 7;
        int nt = idx >> 8;
        int n = nt * 8 + (l >> 2);
        int blk = s >> 2;
        int kb = (s & 3) * 16 + 2 * (l & 3);
        float w00 = head_w(ww, wh, wd, kb, n);
        float w01 = head_w(ww, wh, wd, kb + 1, n);
        float w10 = head_w(ww, wh, wd, kb + 8, n);
        float w11 = head_w(ww, wh, wd, kb + 9, n);
        if (blk) {
            w00 -= bhi(w00); w01 -= bhi(w01);
            w10 -= bhi(w10); w11 -= bhi(w11);
        }
        g_bfrag[idx] = make_uint2(pk_bf(w00, w01), pk_bf(w10, w11));
    }

    // layer-1 B fragments (w1: [in=50][out=50], B[k=in][n=out])
    for (int idx = i; idx < NT1 * 8 * 32; idx += stride) {
        int l = idx & 31;
        int s = (idx >> 5) & 7;
        int nt = idx >> 8;
        int n = nt * 8 + (l >> 2);
        int blk = s >> 2;
        int kb = (s & 3) * 16 + 2 * (l & 3);
        float w00 = 0.f, w01 = 0.f, w10 = 0.f, w11 = 0.f;
        if (n < 50) {
            if (kb < 50) w00 = w1[kb * 50 + n];
            if (kb + 1 < 50) w01 = w1[(kb + 1) * 50 + n];
            if (kb + 8 < 50) w10 = w1[(kb + 8) * 50 + n];
            if (kb + 9 < 50) w11 = w1[(kb + 9) * 50 + n];
        }
        if (blk) {
            w00 -= bhi(w00); w01 -= bhi(w01);
            w10 -= bhi(w10); w11 -= bhi(w11);
        }
        g_b1frag[idx] = make_uint2(pk_bf(w00, w01), pk_bf(w10, w11));
    }

    float* mf = reinterpret_cast<float*>(g_mblob);
    for (int idx = i; idx < MLP_FLOATS; idx += stride) {
        float v = 0.0f;
        if (idx < 400) { int j = idx >> 3, k = idx & 7; v = w0[k * 50 + j]; }
        else if (idx < 452) { int t = idx - 400; v = (t < 50) ? b0[t] : 0.f; }
        else if (idx < 504) { int t = idx - 452; v = (t < 50) ? b1[t] : 0.f; }
        else if (idx < 584) v = 6.0f * bw[idx - 504];
        else if (idx < 664) v = 6.0f * bh[idx - 584];
        else if (idx < 736) v = bd[idx - 664];
        mf[idx] = v;
    }
}

// ---------------- main fused kernel ----------------
__global__ void __launch_bounds__(TPB, 2) nsf_kernel(
    const float* __restrict__ x, float* __restrict__ out, int n, int has_ld) {
    extern __shared__ char smem[];
    uint32_t smem_base = smem_to_u32(smem);
    int tid = threadIdx.x;
    int wid = tid >> 5;
    int lane = tid & 31;

    {
        uint4* sM = reinterpret_cast<uint4*>(smem + SB_MLPB);
        for (int i = tid; i < MLP_FLOATS / 4; i += TPB) sM[i] = g_mblob[i];
    }
    __syncthreads();
    const float* smf = reinterpret_cast<const float*>(smem + SB_MLPB);

    int base = blockIdx.x * TPB;
    int row = base + tid;
    bool valid = (row < n);
    int rr = valid ? row : (n - 1);

    // layer0: x -> h, write split-bf16 h into A
    {
        const float4* xr = reinterpret_cast<const float4*>(x + (size_t)rr * 16);
        float4 x0 = xr[0], x1 = xr[1];
        if (valid) {
            float4* ov = reinterpret_cast<float4*>(out + (size_t)rr * 16);
            ov[0] = x0;
            ov[1] = x1;
        }
        float zd[8] = {x0.x, x0.y, x0.z, x0.w, x1.x, x1.y, x1.z, x1.w};
        uint32_t* arow = reinterpret_cast<uint32_t*>(smem + SB_A + tid * ASTR);
#pragma unroll
        for (int jp = 0; jp < 25; jp++) {
            float h0, h1;
#pragma unroll
            for (int s = 0; s < 2; s++) {
                int j = 2 * jp + s;
                const float4* wv =
                    reinterpret_cast<const float4*>(&smf[MW0T + j * 8]);
                float4 a = wv[0], b = wv[1];
                float acc = smf[MB0 + j];
                acc = fmaf(zd[0], a.x, acc);
                acc = fmaf(zd[1], a.y, acc);
                acc = fmaf(zd[2], a.z, acc);
                acc = fmaf(zd[3], a.w, acc);
                acc = fmaf(zd[4], b.x, acc);
                acc = fmaf(zd[5], b.y, acc);
                acc = fmaf(zd[6], b.z, acc);
                acc = fmaf(zd[7], b.w, acc);
                if (s == 0) h0 = ftanh(acc); else h1 = ftanh(acc);
            }
            arow[jp] = pk_bf(h0, h1);
            arow[32 + jp] = pk_bf(h0 - bhi(h0), h1 - bhi(h1));
        }
#pragma unroll
        for (int jp = 25; jp < 32; jp++) {
            arow[jp] = 0u;
            arow[32 + jp] = 0u;
        }
    }

    // layer-1 B fragments (warps 0..6)
    uint2 B1f[8];
#pragma unroll
    for (int s = 0; s < 8; s++) {
        B1f[s] = (wid < NT1) ? g_b1frag[(wid * 8 + s) * 32 + lane]
                             : make_uint2(0u, 0u);
    }
    __syncthreads();

    // GEMM1 + tanh re-split, 4 quarters of 64 rows
    float* d1 = reinterpret_cast<float*>(smem + SB_D);
#pragma unroll 1
    for (int q = 0; q < 4; q++) {
        if (wid < NT1) {
            int dcol = wid * 8 + ((lane & 3) << 1);
            int drow = lane >> 2;
#pragma unroll
            for (int mt = 0; mt < 4; mt++) {
                uint32_t abase = smem_base + SB_A +
                                 (uint32_t)((q * 4 + mt) * 16 + (lane & 15)) * ASTR +
                                 (uint32_t)((lane >> 4) * 16);
                float D0[4] = {0.f, 0.f, 0.f, 0.f};
#pragma unroll
                for (int s = 0; s < 4; s++) {
                    uint32_t Ah[4], Al[4];
                    LDSM_X4(Ah, abase + s * 32);
                    LDSM_X4(Al, abase + 128 + s * 32);
                    MMA16816(D0, Ah, B1f[s].x, B1f[s].y);
                    MMA16816(D0, Al, B1f[s].x, B1f[s].y);
                    MMA16816(D0, Ah, B1f[4 + s].x, B1f[4 + s].y);
                }
                int dr = mt * 16 + drow;
                *reinterpret_cast<float2*>(d1 + dr * D1STRIDE + dcol) =
                    make_float2(D0[0], D0[1]);
                *reinterpret_cast<float2*>(d1 + (dr + 8) * D1STRIDE + dcol) =
                    make_float2(D0[2], D0[3]);
            }
        }
        __syncthreads();
        // epi1: bias + tanh + re-split into A (rows q*64..q*64+63)
        {
            int rl = tid >> 2;
            int p = tid & 3;
            int jps = p * 7;
            int jpe = (p == 3) ? 25 : (jps + 7);
            uint32_t* arow =
                reinterpret_cast<uint32_t*>(smem + SB_A + (q * 64 + rl) * ASTR);
            const float* drow = d1 + rl * D1STRIDE;
#pragma unroll
            for (int jp = jps; jp < jpe; jp++) {
                float2 v = *reinterpret_cast<const float2*>(drow + 2 * jp);
                float g0 = ftanh(v.x + smf[MB1 + 2 * jp]);
                float g1 = ftanh(v.y + smf[MB1 + 2 * jp + 1]);
                arow[jp] = pk_bf(g0, g1);
                arow[32 + jp] = pk_bf(g0 - bhi(g0), g1 - bhi(g1));
            }
        }
        __syncthreads();
    }

    // head B fragments (persistent regs)
    int cnt = (wid < 5) ? 4 : 3;
    uint2 Bf[4][8];
#pragma unroll
    for (int i = 0; i < 4; i++) {
        if (i < cnt) {
            int nt = wid + 8 * i;
#pragma unroll
            for (int s = 0; s < 8; s++)
                Bf[i][s] = g_bfrag[(nt * 8 + s) * 32 + lane];
        }
    }

    float ld_acc = 0.0f;
    float* dst = reinterpret_cast<float*>(smem + SB_D);
    int drow = lane >> 2, dcol0 = (lane & 3) << 1;

#pragma unroll 1
    for (int it = 0; it < 8; it++) {
#pragma unroll
        for (int half = 0; half < 2; half++) {
            int mt = 2 * it + half;
            uint32_t abase = smem_base + SB_A +
                             (uint32_t)(mt * 16 + (lane & 15)) * ASTR +
                             (uint32_t)((lane >> 4) * 16);
            float D0[4][4];
#pragma unroll
            for (int i = 0; i < 4; i++)
#pragma unroll
                for (int qq = 0; qq < 4; qq++) D0[i][qq] = 0.f;

#pragma unroll
            for (int s = 0; s < 4; s++) {
                uint32_t Ah[4], Al[4];
                LDSM_X4(Ah, abase + s * 32);
                LDSM_X4(Al, abase + 128 + s * 32);
#pragma unroll
                for (int i = 0; i < 4; i++) {
                    if (i < cnt) {
                        MMA16816(D0[i], Ah, Bf[i][s].x, Bf[i][s].y);
                        MMA16816(D0[i], Al, Bf[i][s].x, Bf[i][s].y);
                        MMA16816(D0[i], Ah, Bf[i][4 + s].x, Bf[i][4 + s].y);
                    }
                }
            }
#pragma unroll
            for (int i = 0; i < 4; i++) {
                if (i < cnt) {
                    int dc = (wid + 8 * i) * 8 + dcol0;
                    int dr = half * 16 + drow;
                    *reinterpret_cast<float2*>(dst + dr * DSTRIDE + dc) =
                        make_float2(D0[i][0], D0[i][1]);
                    *reinterpret_cast<float2*>(dst + (dr + 8) * DSTRIDE + dc) =
                        make_float2(D0[i][2], D0[i][3]);
                }
            }
        }
        __syncthreads();

        // epi2: 256 threads = 32 rows x 8 dims
        {
            int lrow = tid >> 3;
            int dd = tid & 7;
            int grow = base + it * 32 + lrow;
            bool gvalid = (grow < n);
            int gr = gvalid ? grow : (n - 1);
            const float* dr = dst + lrow * DSTRIDE + dd * 29;

            float ew[KB], eh[KB], dv[KB - 1];
            float sw = 0.f, sh = 0.f;
#pragma unroll
            for (int j = 0; j < KB; j++) {
                ew[j] = __expf(dr[j] + smf[MBW + dd * 10 + j]);
                sw += ew[j];
                eh[j] = __expf(dr[10 + j] + smf[MBH + dd * 10 + j]);
                sh += eh[j];
            }
#pragma unroll
            for (int j = 0; j < KB - 1; j++) {
                dv[j] = fsoftplus(dr[20 + j] + smf[MBD + dd * 9 + j]);
            }
            float uu = __ldg(x + (size_t)gr * 16 + 8 + dd);
            float z;
            float ldet = spline_eval(uu, ew, eh, dv, sw, sh, z);
            if (gvalid) {
                out[(size_t)grow * 16 + 8 + dd] = z;
                ld_acc += ldet;
            }
        }
        __syncthreads();
    }

    // logdet reduction
    float* s_red = reinterpret_cast<float*>(smem + SB_RED);
    double* s_dred = reinterpret_cast<double*>(smem + SB_DRED);
#pragma unroll
    for (int off = 16; off > 0; off >>= 1)
        ld_acc += __shfl_down_sync(0xffffffffu, ld_acc, off);
    if (lane == 0) s_red[wid] = ld_acc;
    __syncthreads();
    if (tid == 0) {
        float t = 0.f;
#pragma unroll
        for (int i = 0; i < TPB / 32; i++) t += s_red[i];
        g_partial[blockIdx.x] = t;
        __threadfence();
        unsigned int done = atomicAdd(&g_count, 1u);
        s_red[0] = (done == gridDim.x - 1) ? 1.0f : 0.0f;
    }
    __syncthreads();
    if (s_red[0] != 0.0f) {
        __threadfence();
        int nb = gridDim.x;
        double acc = 0.0;
        for (int i = tid; i < nb; i += TPB) acc += (double)g_partial[i];
#pragma unroll
        for (int off = 16; off > 0; off >>= 1)
            acc += __shfl_down_sync(0xffffffffu, acc, off);
        if (lane == 0) s_dred[wid] = acc;
        __syncthreads();
        if (tid == 0) {
            double t = 0.0;
#pragma unroll
            for (int i = 0; i < TPB / 32; i++) t += s_dred[i];
            if (has_ld) out[(size_t)n * 16] = (float)t;
            g_count = 0;
        }
    }
}

extern "C" void kernel_launch(void* const* d_in, const int* in_sizes, int n_in,
                              void* d_out, int out_size) {
    const float* x  = (const float*)d_in[0];
    const float* w0 = (const float*)d_in[1];
    const float* b0 = (const float*)d_in[2];
    const float* w1 = (const float*)d_in[3];
    const float* b1 = (const float*)d_in[4];
    const float* ww = (const float*)d_in[5];
    const float* bw = (const float*)d_in[6];
    const float* wh = (const float*)d_in[7];
    const float* bh = (const float*)d_in[8];
    const float* wd = (const float*)d_in[9];
    const float* bd = (const float*)d_in[10];
    float* out = (float*)d_out;

    int n = in_sizes[0] / 16;
    int nblocks = (n + TPB - 1) / TPB;
    int has_ld = (out_size > n * 16) ? 1 : 0;

    cudaFuncSetAttribute(nsf_kernel, cudaFuncAttributeMaxDynamicSharedMemorySize,
                         SMEM_BYTES);

    prep_kernel<<<40, 256>>>(w0, b0, w1, b1, ww, bw, wh, bh, wd, bd);
    nsf_kernel<<<nblocks, TPB, SMEM_BYTES>>>(x, out, n, has_ld);
}